// round 5
// baseline (speedup 1.0000x reference)
#include <cuda_runtime.h>
#include <math.h>

#define TT 2048
#define NCTA 128

__device__ float g_MT[1024 * 256];                    // folded init matrix, [j][d]
__device__ float g_abias[1024];                       // folded layer0 bias
__device__ float g_A0[(size_t)TT * 32 * 1024];        // layer0 input gates [t][b][j]
__device__ float g_h0buf[3][32 * 256];
__device__ float g_h1buf[3][32 * 256];
__device__ volatile unsigned g_flags[NCTA * 32];      // 128B-padded per-CTA step flags

__device__ __forceinline__ float sigf(float x) {
    return __fdividef(1.f, 1.f + __expf(-x));
}
__device__ __forceinline__ float tanha(float x) {
    float y; asm("tanh.approx.f32 %0, %1;" : "=f"(y) : "f"(x)); return y;
}
__device__ __forceinline__ void ffma2(unsigned long long& d,
                                      unsigned long long a, unsigned long long b) {
    asm("fma.rn.f32x2 %0, %1, %2, %0;" : "+l"(d) : "l"(a), "l"(b));
}
__device__ __forceinline__ unsigned ld_acq(const volatile unsigned* p) {
    unsigned v;
    asm volatile("ld.acquire.gpu.u32 %0, [%1];"
                 : "=r"(v) : "l"((const unsigned*)p) : "memory");
    return v;
}

// ---- K1a: MT[j][d] = sum_h Wih0[j,h] * Winit[h,d] --------------------------
__global__ void k1_mt(const float* __restrict__ Wih, const float* __restrict__ Winit) {
    int d = (blockIdx.x & 7) * 32 + (threadIdx.x & 31);
    int j = (blockIdx.x >> 3) * 8 + (threadIdx.x >> 5);
    const float* wr = Wih + (size_t)j * 256;
    float s = 0.f;
#pragma unroll 4
    for (int h = 0; h < 256; ++h)
        s = fmaf(wr[h], Winit[(size_t)h * 256 + d], s);
    g_MT[(size_t)j * 256 + d] = s;
}

// ---- K1b: abias[j] = Wih0[j,:]·b_init + bih0[j] + bhh0[j] ------------------
__global__ void k1_bias(const float* __restrict__ Wih, const float* __restrict__ binit,
                        const float* __restrict__ bih, const float* __restrict__ bhh) {
    int j = blockIdx.x * 256 + threadIdx.x;
    const float* wr = Wih + (size_t)j * 256;
    float s = bih[j] + bhh[j];
#pragma unroll 4
    for (int h = 0; h < 256; ++h) s = fmaf(wr[h], binit[h], s);
    g_abias[j] = s;
}

// ---- K2: A0 = input @ MT^T + abias (65536 x 1024 x 256, f32x2-packed) ------
__global__ __launch_bounds__(256) void k2_gemm(const float* __restrict__ A) {
    __shared__ float As[128][20];   // [m][k-tile], padded to 20 floats
    __shared__ float Bs[64][20];    // [c][k-tile]
    const int tid = threadIdx.x;
    const int rowBase = blockIdx.y * 128;
    const int colBase = blockIdx.x * 64;
    const int ty = tid >> 4, tx = tid & 15;

    unsigned long long acc[8][4];
#pragma unroll
    for (int i = 0; i < 8; ++i)
#pragma unroll
        for (int c = 0; c < 4; ++c) acc[i][c] = 0ull;

    for (int kt = 0; kt < 256; kt += 16) {
#pragma unroll
        for (int rep = 0; rep < 2; ++rep) {
            int e = tid + rep * 256;          // 0..511
            int m = e >> 2, q = e & 3;
            *(float4*)&As[m][q * 4] =
                *(const float4*)(A + (size_t)(rowBase + m) * 256 + kt + q * 4);
        }
        {
            int c = tid >> 2, q = tid & 3;
            *(float4*)&Bs[c][q * 4] =
                *(const float4*)(g_MT + (size_t)(colBase + c) * 256 + kt + q * 4);
        }
        __syncthreads();
#pragma unroll
        for (int q = 0; q < 4; ++q) {
            ulonglong2 bp[4];
#pragma unroll
            for (int c = 0; c < 4; ++c)
                bp[c] = *(const ulonglong2*)&Bs[tx * 4 + c][q * 4];
#pragma unroll
            for (int i = 0; i < 8; ++i) {
                ulonglong2 ap = *(const ulonglong2*)&As[ty * 8 + i][q * 4];
#pragma unroll
                for (int c = 0; c < 4; ++c) {
                    ffma2(acc[i][c], ap.x, bp[c].x);
                    ffma2(acc[i][c], ap.y, bp[c].y);
                }
            }
        }
        __syncthreads();
    }
    float4 bias = *(const float4*)(g_abias + colBase + tx * 4);
#pragma unroll
    for (int i = 0; i < 8; ++i) {
        float4 r;
        float2 u0 = *(float2*)&acc[i][0]; r.x = u0.x + u0.y + bias.x;
        float2 u1 = *(float2*)&acc[i][1]; r.y = u1.x + u1.y + bias.y;
        float2 u2 = *(float2*)&acc[i][2]; r.z = u2.x + u2.y + bias.z;
        float2 u3 = *(float2*)&acc[i][3]; r.w = u3.x + u3.y + bias.w;
        *(float4*)(g_A0 + (size_t)(rowBase + ty * 8 + i) * 1024 + colBase + tx * 4) = r;
    }
}

// ---- K3: persistent recurrent kernel -------------------------------------
// 128 CTAs x 256 thr, 1 CTA/SM. CTA owns hidden cols {2bx, 2bx+1} of BOTH
// layers. Phase p computes h1[p-1] and h0[p]. f32x2 FFMA, flag barrier.
// SMEM floats: sw 0..6240 (3x8x260), sh0 6240, sh1 14560, sb1 22880,
// sc0 22888, sc1 22952, f0 22016... actually sf at 23016; total 23017 floats.
__global__ __launch_bounds__(256, 1) void k3_rec(
    const float* __restrict__ Wih, const float* __restrict__ Whh,
    const float* __restrict__ bih, const float* __restrict__ bhh,
    const float* __restrict__ h0in, const float* __restrict__ c0in,
    float* __restrict__ out)
{
    extern __shared__ float sm[];
    float* sw  = sm;
    float* sh0 = sm + 6240;
    float* sh1 = sm + 14560;
    float* sb1 = sm + 22880;
    float* sc0 = sm + 22888;
    float* sc1 = sm + 22952;
    unsigned* sf = (unsigned*)(sm + 23016);

    const int tid = threadIdx.x;
    const int bx = blockIdx.x;
    const int hc0 = bx * 2;
    const int lane = tid & 31, wp = tid >> 5;
    const int r = lane & 7;                 // gate row: g = r>>1, u = r&1
    const int bg = wp * 4 + (lane >> 3);    // batch 0..31

    // persistent weights: m0=Whh0, m1=Wih1, m2=Whh1 (layer stride 262144)
    for (int e = tid; e < 1536; e += 256) {
        int m = e >> 9, rr = (e >> 6) & 7, q = e & 63;
        int j = (rr >> 1) * 256 + hc0 + (rr & 1);
        const float* base = (m == 0) ? (Whh + (size_t)j * 256)
                          : (m == 1) ? (Wih + 262144 + (size_t)j * 256)
                                     : (Whh + 262144 + (size_t)j * 256);
        *(float4*)&sw[(m * 8 + rr) * 260 + q * 4] = *(const float4*)(base + q * 4);
    }
    if (tid < 8) {
        int j = (tid >> 1) * 256 + hc0 + (tid & 1);
        sb1[tid] = bih[1024 + j] + bhh[1024 + j];
    }
    if (tid < 64) {
        int b = tid >> 1, u = tid & 1;
        sc0[tid] = c0in[b * 256 + hc0 + u];
        sc1[tid] = c0in[8192 + b * 256 + hc0 + u];
    }
    if (tid == 0) *sf = g_flags[bx * 32];   // flag base (equal across CTAs)
    __syncthreads();
    const unsigned f0 = *sf;

    const float b1 = sb1[r];
    const float* wr0 = sw + r * 260;
    const float* wr1 = sw + (8 + r) * 260;
    const float* wr2 = sw + (16 + r) * 260;
    const float* hb0 = sh0 + bg * 260;
    const float* hb1 = sh1 + bg * 260;
    const size_t a0idx = (size_t)bg * 1024 + (r >> 1) * 256 + hc0 + (r & 1);

    for (int p = 0; p <= TT; ++p) {
        float a0v = 0.f;
        if (p < TT) a0v = __ldcs(g_A0 + (size_t)p * 32768 + a0idx);

        const float* s0 = (p == 0) ? h0in : g_h0buf[(p - 1) % 3];
        const float* s1 = (p <= 1) ? (h0in + 8192) : g_h1buf[(p - 1) % 3];
#pragma unroll
        for (int i = 0; i < 8; ++i) {
            int f4 = tid + i * 256;
            int b = f4 >> 6, k4 = f4 & 63;
            float4 v0 = __ldcg((const float4*)(s0 + b * 256 + k4 * 4));
            float4 v1 = __ldcg((const float4*)(s1 + b * 256 + k4 * 4));
            *(float4*)&sh0[b * 260 + k4 * 4] = v0;
            *(float4*)&sh1[b * 260 + k4 * 4] = v1;
        }
        __syncthreads();

        unsigned long long acc0 = 0ull, acc1 = 0ull, acc2 = 0ull;
#pragma unroll 8
        for (int k = 0; k < 64; ++k) {
            ulonglong2 h0v = *(const ulonglong2*)(hb0 + k * 4);
            ulonglong2 h1v = *(const ulonglong2*)(hb1 + k * 4);
            ulonglong2 w0v = *(const ulonglong2*)(wr0 + k * 4);
            ulonglong2 w1v = *(const ulonglong2*)(wr1 + k * 4);
            ulonglong2 w2v = *(const ulonglong2*)(wr2 + k * 4);
            ffma2(acc0, h0v.x, w0v.x); ffma2(acc0, h0v.y, w0v.y);
            ffma2(acc1, h0v.x, w1v.x); ffma2(acc1, h0v.y, w1v.y);
            ffma2(acc2, h1v.x, w2v.x); ffma2(acc2, h1v.y, w2v.y);
        }
        float2 u0 = *(float2*)&acc0;
        float2 u1 = *(float2*)&acc1;
        float2 u2 = *(float2*)&acc2;
        float gv0 = a0v + u0.x + u0.y;              // layer0 gate (bias in A0)
        float gv1 = u1.x + u1.y + u2.x + u2.y + b1; // layer1 gate
        float f0g = __shfl_down_sync(0xffffffffu, gv0, 2);
        float gg0 = __shfl_down_sync(0xffffffffu, gv0, 4);
        float o0  = __shfl_down_sync(0xffffffffu, gv0, 6);
        float f1g = __shfl_down_sync(0xffffffffu, gv1, 2);
        float gg1 = __shfl_down_sync(0xffffffffu, gv1, 4);
        float o1  = __shfl_down_sync(0xffffffffu, gv1, 6);
        if (r < 2) {
            int ci = bg * 2 + r, col = hc0 + r;
            if (p < TT) {
                float c = sc0[ci];
                float cn = fmaf(sigf(f0g), c, sigf(gv0) * tanha(gg0));
                float hn = sigf(o0) * tanha(cn);
                sc0[ci] = cn;
                __stcg(g_h0buf[p % 3] + bg * 256 + col, hn);
            }
            if (p >= 1) {
                float c = sc1[ci];
                float cn = fmaf(sigf(f1g), c, sigf(gv1) * tanha(gg1));
                float hn = sigf(o1) * tanha(cn);
                sc1[ci] = cn;
                __stcg(g_h1buf[p % 3] + bg * 256 + col, hn);
                out[(size_t)(p - 1) * 16384 + bg * 512 + col] = hn;
            }
        }
        // ---- distributed flag barrier (all 128 CTAs co-resident) ----
        __syncthreads();
        unsigned tgt = f0 + (unsigned)(p + 1);
        if (tid == 0) {
            __threadfence();
            g_flags[bx * 32] = tgt;
        }
        if (tid < NCTA) {
            while (ld_acq(&g_flags[tid * 32]) < tgt) { }
        }
        __syncthreads();
    }
}

// ---- K4: backward half = h1[T-1] broadcast over t --------------------------
__global__ void k4_fill(float* __restrict__ out) {
    size_t i = (size_t)blockIdx.x * 256 + threadIdx.x;   // over 2048*32*64 f4
    int u4 = (int)(i & 63);
    size_t tb = i >> 6;
    int b = (int)(tb & 31);
    float4 v = *(const float4*)(out + (size_t)2047 * 16384 + b * 512 + u4 * 4);
    *(float4*)(out + tb * 512 + 256 + u4 * 4) = v;
}

extern "C" void kernel_launch(void* const* d_in, const int* in_sizes, int n_in,
                              void* d_out, int out_size) {
    const float* input = (const float*)d_in[0];
    const float* Winit = (const float*)d_in[1];
    const float* binit = (const float*)d_in[2];
    const float* Wih   = (const float*)d_in[3];
    const float* Whh   = (const float*)d_in[4];
    const float* bih   = (const float*)d_in[5];
    const float* bhh   = (const float*)d_in[6];
    const float* h0in  = (const float*)d_in[7];
    const float* c0in  = (const float*)d_in[8];
    float* out = (float*)d_out;

    cudaFuncSetAttribute(k3_rec, cudaFuncAttributeMaxDynamicSharedMemorySize, 92080);

    k1_mt<<<1024, 256>>>(Wih, Winit);
    k1_bias<<<4, 256>>>(Wih, binit, bih, bhh);
    k2_gemm<<<dim3(16, 512), 256>>>(input);
    k3_rec<<<NCTA, 256, 92080>>>(Wih, Whh, bih, bhh, h0in, c0in, out);
    k4_fill<<<16384, 256>>>(out);
}

// round 6
// speedup vs baseline: 1.1262x; 1.1262x over previous
#include <cuda_runtime.h>
#include <math.h>

#define TT 2048
#define NCTA 128

__device__ float g_MT[256 * 1024];                    // folded init matrix, [d][j]
__device__ float g_abias[1024];                       // folded layer0 bias
__device__ float g_A0[(size_t)TT * 32 * 1024];        // layer0 input gates [t][b][j]
__device__ float g_h0buf[3][32 * 256];
__device__ float g_h1buf[3][32 * 256];
__device__ volatile unsigned g_flags[NCTA * 32];      // 128B-padded per-CTA step flags

__device__ __forceinline__ float sigf(float x) {
    return __fdividef(1.f, 1.f + __expf(-x));
}
__device__ __forceinline__ float tanha(float x) {
    float y; asm("tanh.approx.f32 %0, %1;" : "=f"(y) : "f"(x)); return y;
}
__device__ __forceinline__ void ffma2(unsigned long long& d,
                                      unsigned long long a, unsigned long long b) {
    asm("fma.rn.f32x2 %0, %1, %2, %0;" : "+l"(d) : "l"(a), "l"(b));
}
__device__ __forceinline__ unsigned ld_rlx(const volatile unsigned* p) {
    unsigned v;
    asm volatile("ld.relaxed.gpu.u32 %0, [%1];"
                 : "=r"(v) : "l"((const unsigned*)p) : "memory");
    return v;
}
__device__ __forceinline__ void st_rel(volatile unsigned* p, unsigned v) {
    asm volatile("st.release.gpu.u32 [%0], %1;"
                 :: "l"((unsigned*)p), "r"(v) : "memory");
}

// ---- K1a: MT[d][j] = sum_h Wih0[j,h] * Winit[h,d] --------------------------
__global__ void k1_mt(const float* __restrict__ Wih, const float* __restrict__ Winit) {
    int d = (blockIdx.x & 7) * 32 + (threadIdx.x & 31);
    int j = (blockIdx.x >> 3) * 8 + (threadIdx.x >> 5);
    const float* wr = Wih + (size_t)j * 256;
    float s = 0.f;
#pragma unroll 4
    for (int h = 0; h < 256; ++h)
        s = fmaf(wr[h], Winit[(size_t)h * 256 + d], s);
    g_MT[(size_t)d * 1024 + j] = s;
}

// ---- K1b: abias[j] = Wih0[j,:]·b_init + bih0[j] + bhh0[j] ------------------
__global__ void k1_bias(const float* __restrict__ Wih, const float* __restrict__ binit,
                        const float* __restrict__ bih, const float* __restrict__ bhh) {
    int j = blockIdx.x * 256 + threadIdx.x;
    const float* wr = Wih + (size_t)j * 256;
    float s = bih[j] + bhh[j];
#pragma unroll 4
    for (int h = 0; h < 256; ++h) s = fmaf(wr[h], binit[h], s);
    g_abias[j] = s;
}

// ---- K2: A0 = input @ MT + abias  (65536 x 1024 x 256 SGEMM, R4 version) ---
__global__ __launch_bounds__(256) void k2_gemm(const float* __restrict__ A) {
    __shared__ float As[16][132];
    __shared__ float Bs[16][64];
    const int tid = threadIdx.x;
    const int rowBase = blockIdx.y * 128;
    const int colBase = blockIdx.x * 64;
    const int ty = tid >> 4, tx = tid & 15;

    float acc[8][4];
#pragma unroll
    for (int i = 0; i < 8; ++i)
#pragma unroll
        for (int c = 0; c < 4; ++c) acc[i][c] = 0.f;

    for (int kt = 0; kt < 256; kt += 16) {
#pragma unroll
        for (int rep = 0; rep < 2; ++rep) {
            int e = tid + rep * 256;
            int m = e >> 2, q = e & 3;
            float4 v = *(const float4*)(A + (size_t)(rowBase + m) * 256 + kt + q * 4);
            As[q * 4 + 0][m] = v.x; As[q * 4 + 1][m] = v.y;
            As[q * 4 + 2][m] = v.z; As[q * 4 + 3][m] = v.w;
        }
        {
            int kr = tid >> 4, q = tid & 15;
            *(float4*)&Bs[kr][q * 4] =
                *(const float4*)(g_MT + (size_t)(kt + kr) * 1024 + colBase + q * 4);
        }
        __syncthreads();
#pragma unroll
        for (int k = 0; k < 16; ++k) {
            float4 bv = *(float4*)&Bs[k][tx * 4];
            float4 a0 = *(float4*)&As[k][ty * 8];
            float4 a1 = *(float4*)&As[k][ty * 8 + 4];
#define FM(i, av) acc[i][0]=fmaf(av,bv.x,acc[i][0]); acc[i][1]=fmaf(av,bv.y,acc[i][1]); \
                  acc[i][2]=fmaf(av,bv.z,acc[i][2]); acc[i][3]=fmaf(av,bv.w,acc[i][3]);
            FM(0, a0.x) FM(1, a0.y) FM(2, a0.z) FM(3, a0.w)
            FM(4, a1.x) FM(5, a1.y) FM(6, a1.z) FM(7, a1.w)
#undef FM
        }
        __syncthreads();
    }
    float4 bias = *(const float4*)(g_abias + colBase + tx * 4);
#pragma unroll
    for (int i = 0; i < 8; ++i) {
        float4 r;
        r.x = acc[i][0] + bias.x; r.y = acc[i][1] + bias.y;
        r.z = acc[i][2] + bias.z; r.w = acc[i][3] + bias.w;
        *(float4*)(g_A0 + (size_t)(rowBase + ty * 8 + i) * 1024 + colBase + tx * 4) = r;
    }
}

// ---- K3: persistent recurrent kernel, 512 thr ------------------------------
// 128 CTAs x 512 thr, 1 CTA/SM. CTA owns hidden cols {2bx,2bx+1} of BOTH
// layers. Phase p computes h1[p-1] and h0[p].
// Thread map: warp w: kh = w&3 (k-quarter), grp = w>>2; lane: bp = grp*4 +
// (lane>>3), r = lane&7 (gate row: g=r>>1, u=r&1); bg0=2bp, bg1=2bp+1.
// SMEM floats: sw 0 (3x8x260=6240), sh0 6240, sh1 14560, sb1 22880,
// sc0 22888, sc1 22952, sf 23016(2), sred 23018 (2304 ull = 4608 fl);
// total 27626 floats = 110504 B.
__global__ __launch_bounds__(512, 1) void k3_rec(
    const float* __restrict__ Wih, const float* __restrict__ Whh,
    const float* __restrict__ bih, const float* __restrict__ bhh,
    const float* __restrict__ h0in, const float* __restrict__ c0in,
    float* __restrict__ out)
{
    extern __shared__ float sm[];
    float* sw  = sm;
    float* sh0 = sm + 6240;
    float* sh1 = sm + 14560;
    float* sb1 = sm + 22880;
    float* sc0 = sm + 22888;
    float* sc1 = sm + 22952;
    unsigned* sf = (unsigned*)(sm + 23016);
    unsigned long long* sred = (unsigned long long*)(sm + 23018);

    const int tid = threadIdx.x;
    const int bx = blockIdx.x;
    const int hc0 = bx * 2;
    const int lane = tid & 31, w = tid >> 5;
    const int kh = w & 3, grp = w >> 2;
    const int bp = grp * 4 + (lane >> 3);
    const int r = lane & 7;
    const int bg0 = bp * 2, bg1 = bp * 2 + 1;

    // persistent weights: m0=Whh0, m1=Wih1, m2=Whh1 (layer stride 262144)
    for (int e = tid; e < 1536; e += 512) {
        int m = e >> 9, rr = (e >> 6) & 7, q = e & 63;
        int j = (rr >> 1) * 256 + hc0 + (rr & 1);
        const float* base = (m == 0) ? (Whh + (size_t)j * 256)
                          : (m == 1) ? (Wih + 262144 + (size_t)j * 256)
                                     : (Whh + 262144 + (size_t)j * 256);
        *(float4*)&sw[(m * 8 + rr) * 260 + q * 4] = *(const float4*)(base + q * 4);
    }
    if (tid < 8) {
        int j = (tid >> 1) * 256 + hc0 + (tid & 1);
        sb1[tid] = bih[1024 + j] + bhh[1024 + j];
    }
    if (tid < 64) {
        int b = tid >> 1, u = tid & 1;
        sc0[tid] = c0in[b * 256 + hc0 + u];
        sc1[tid] = c0in[8192 + b * 256 + hc0 + u];
    }
    if (tid == 0) *sf = g_flags[bx * 32];
    __syncthreads();
    const unsigned f0 = *sf;
    const float b1v = sb1[r];

    const float* wp0 = sw + r * 260 + kh * 64;
    const float* wp1 = wp0 + 8 * 260;
    const float* wp2 = wp0 + 16 * 260;
    const float* h0a = sh0 + bg0 * 260 + kh * 64;
    const float* h0b = sh0 + bg1 * 260 + kh * 64;
    const float* h1a = sh1 + bg0 * 260 + kh * 64;
    const float* h1b = sh1 + bg1 * 260 + kh * 64;
    const int slotA = (bg0 * 8 + r) * 3;
    const int slotB = (bg1 * 8 + r) * 3;
    const size_t a0iA = (size_t)bg0 * 1024 + (r >> 1) * 256 + hc0 + (r & 1);
    const size_t a0iB = (size_t)bg1 * 1024 + (r >> 1) * 256 + hc0 + (r & 1);

    for (int p = 0; p <= TT; ++p) {
        float a0vA = 0.f, a0vB = 0.f;
        if (kh == 0 && p < TT) {
            a0vA = __ldcs(g_A0 + (size_t)p * 32768 + a0iA);
            a0vB = __ldcs(g_A0 + (size_t)p * 32768 + a0iB);
        }
        // ---- stage h0[p-1], h1[p-2] into SMEM (L2-coherent loads) ----
        const float* s0 = (p == 0) ? h0in : g_h0buf[(p - 1) % 3];
        const float* s1 = (p <= 1) ? (h0in + 8192) : g_h1buf[(p - 1) % 3];
#pragma unroll
        for (int i = 0; i < 4; ++i) {
            int f4 = tid + i * 512;
            int b = f4 >> 6, k4 = f4 & 63;
            float4 v0 = __ldcg((const float4*)(s0 + b * 256 + k4 * 4));
            float4 v1 = __ldcg((const float4*)(s1 + b * 256 + k4 * 4));
            *(float4*)&sh0[b * 260 + k4 * 4] = v0;
            *(float4*)&sh1[b * 260 + k4 * 4] = v1;
        }
        __syncthreads();

        unsigned long long a0A = 0ull, a0B = 0ull, a1A = 0ull,
                           a1B = 0ull, a2A = 0ull, a2B = 0ull;
#pragma unroll
        for (int q = 0; q < 16; ++q) {
            ulonglong2 w0 = *(const ulonglong2*)(wp0 + q * 4);
            ulonglong2 w1 = *(const ulonglong2*)(wp1 + q * 4);
            ulonglong2 w2 = *(const ulonglong2*)(wp2 + q * 4);
            ulonglong2 hA = *(const ulonglong2*)(h0a + q * 4);
            ulonglong2 hB = *(const ulonglong2*)(h0b + q * 4);
            ulonglong2 gA = *(const ulonglong2*)(h1a + q * 4);
            ulonglong2 gB = *(const ulonglong2*)(h1b + q * 4);
            ffma2(a0A, w0.x, hA.x); ffma2(a0A, w0.y, hA.y);
            ffma2(a0B, w0.x, hB.x); ffma2(a0B, w0.y, hB.y);
            ffma2(a1A, w1.x, hA.x); ffma2(a1A, w1.y, hA.y);
            ffma2(a1B, w1.x, hB.x); ffma2(a1B, w1.y, hB.y);
            ffma2(a2A, w2.x, gA.x); ffma2(a2A, w2.y, gA.y);
            ffma2(a2B, w2.x, gB.x); ffma2(a2B, w2.y, gB.y);
        }
        if (kh != 0) {
            unsigned long long* d = sred + (size_t)(kh - 1) * 768;
            d[slotA + 0] = a0A; d[slotA + 1] = a1A; d[slotA + 2] = a2A;
            d[slotB + 0] = a0B; d[slotB + 1] = a1B; d[slotB + 2] = a2B;
        }
        __syncthreads();

        if (kh == 0) {
            float2 p0A = *(float2*)&a0A, p1A = *(float2*)&a1A, p2A = *(float2*)&a2A;
            float2 p0B = *(float2*)&a0B, p1B = *(float2*)&a1B, p2B = *(float2*)&a2B;
#pragma unroll
            for (int kk = 0; kk < 3; ++kk) {
                const unsigned long long* d = sred + (size_t)kk * 768;
                float2 q0 = *(float2*)&d[slotA + 0]; p0A.x += q0.x; p0A.y += q0.y;
                float2 q1 = *(float2*)&d[slotA + 1]; p1A.x += q1.x; p1A.y += q1.y;
                float2 q2 = *(float2*)&d[slotA + 2]; p2A.x += q2.x; p2A.y += q2.y;
                float2 q3 = *(float2*)&d[slotB + 0]; p0B.x += q3.x; p0B.y += q3.y;
                float2 q4 = *(float2*)&d[slotB + 1]; p1B.x += q4.x; p1B.y += q4.y;
                float2 q5 = *(float2*)&d[slotB + 2]; p2B.x += q5.x; p2B.y += q5.y;
            }
            float gv0A = a0vA + p0A.x + p0A.y;
            float gv0B = a0vB + p0B.x + p0B.y;
            float gv1A = p1A.x + p1A.y + p2A.x + p2A.y + b1v;
            float gv1B = p1B.x + p1B.y + p2B.x + p2B.y + b1v;
            float f0A = __shfl_down_sync(0xffffffffu, gv0A, 2);
            float g0A = __shfl_down_sync(0xffffffffu, gv0A, 4);
            float o0A = __shfl_down_sync(0xffffffffu, gv0A, 6);
            float f0B = __shfl_down_sync(0xffffffffu, gv0B, 2);
            float g0B = __shfl_down_sync(0xffffffffu, gv0B, 4);
            float o0B = __shfl_down_sync(0xffffffffu, gv0B, 6);
            float f1A = __shfl_down_sync(0xffffffffu, gv1A, 2);
            float g1A = __shfl_down_sync(0xffffffffu, gv1A, 4);
            float o1A = __shfl_down_sync(0xffffffffu, gv1A, 6);
            float f1B = __shfl_down_sync(0xffffffffu, gv1B, 2);
            float g1B = __shfl_down_sync(0xffffffffu, gv1B, 4);
            float o1B = __shfl_down_sync(0xffffffffu, gv1B, 6);
            if (r < 2) {
                int u = r;
                int ciA = bg0 * 2 + u, ciB = bg1 * 2 + u, col = hc0 + u;
                if (p < TT) {
                    float cA = sc0[ciA];
                    float cnA = fmaf(sigf(f0A), cA, sigf(gv0A) * tanha(g0A));
                    sc0[ciA] = cnA;
                    __stcg(g_h0buf[p % 3] + bg0 * 256 + col, sigf(o0A) * tanha(cnA));
                    float cB = sc0[ciB];
                    float cnB = fmaf(sigf(f0B), cB, sigf(gv0B) * tanha(g0B));
                    sc0[ciB] = cnB;
                    __stcg(g_h0buf[p % 3] + bg1 * 256 + col, sigf(o0B) * tanha(cnB));
                }
                if (p >= 1) {
                    float cA = sc1[ciA];
                    float cnA = fmaf(sigf(f1A), cA, sigf(gv1A) * tanha(g1A));
                    float hnA = sigf(o1A) * tanha(cnA);
                    sc1[ciA] = cnA;
                    __stcg(g_h1buf[p % 3] + bg0 * 256 + col, hnA);
                    out[(size_t)(p - 1) * 16384 + bg0 * 512 + col] = hnA;
                    float cB = sc1[ciB];
                    float cnB = fmaf(sigf(f1B), cB, sigf(gv1B) * tanha(g1B));
                    float hnB = sigf(o1B) * tanha(cnB);
                    sc1[ciB] = cnB;
                    __stcg(g_h1buf[p % 3] + bg1 * 256 + col, hnB);
                    out[(size_t)(p - 1) * 16384 + bg1 * 512 + col] = hnB;
                }
                __threadfence();   // order h stores before the flag release
            }
        }
        // ---- distributed flag barrier (all 128 CTAs co-resident) ----
        __syncthreads();
        unsigned tgt = f0 + (unsigned)(p + 1);
        if (tid == 0) st_rel(&g_flags[bx * 32], tgt);
        if (tid < NCTA) {
            while (ld_rlx(&g_flags[tid * 32]) < tgt) { }
            __threadfence();   // acquire
        }
        __syncthreads();
    }
}

// ---- K4: backward half = h1[T-1] broadcast over t --------------------------
__global__ void k4_fill(float* __restrict__ out) {
    size_t i = (size_t)blockIdx.x * 256 + threadIdx.x;   // over 2048*32*64 f4
    int u4 = (int)(i & 63);
    size_t tb = i >> 6;
    int b = (int)(tb & 31);
    float4 v = *(const float4*)(out + (size_t)2047 * 16384 + b * 512 + u4 * 4);
    *(float4*)(out + tb * 512 + 256 + u4 * 4) = v;
}

extern "C" void kernel_launch(void* const* d_in, const int* in_sizes, int n_in,
                              void* d_out, int out_size) {
    const float* input = (const float*)d_in[0];
    const float* Winit = (const float*)d_in[1];
    const float* binit = (const float*)d_in[2];
    const float* Wih   = (const float*)d_in[3];
    const float* Whh   = (const float*)d_in[4];
    const float* bih   = (const float*)d_in[5];
    const float* bhh   = (const float*)d_in[6];
    const float* h0in  = (const float*)d_in[7];
    const float* c0in  = (const float*)d_in[8];
    float* out = (float*)d_out;

    cudaFuncSetAttribute(k3_rec, cudaFuncAttributeMaxDynamicSharedMemorySize, 110504);

    k1_mt<<<1024, 256>>>(Wih, Winit);
    k1_bias<<<4, 256>>>(Wih, binit, bih, bhh);
    k2_gemm<<<dim3(16, 512), 256>>>(input);
    k3_rec<<<NCTA, 512, 110504>>>(Wih, Whh, bih, bhh, h0in, c0in, out);
    k4_fill<<<16384, 256>>>(out);
}

// round 7
// speedup vs baseline: 1.2430x; 1.1037x over previous
#include <cuda_runtime.h>
#include <math.h>

#define TT 2048

__device__ float g_MT[256 * 1024];                    // folded init matrix, [d][j]
__device__ float g_abias[1024];                       // folded layer0 bias
__device__ float g_A0[(size_t)TT * 32 * 1024];        // layer0 input gates [t][b][j]
__device__ float g_h0buf[3][32 * 256];
__device__ float g_h1buf[3][32 * 256];
__device__ volatile unsigned g_flags[128 * 32];       // 128B-padded per-CTA step flags

__device__ __forceinline__ float sigf(float x) {
    return __fdividef(1.f, 1.f + __expf(-x));
}
__device__ __forceinline__ float tanha(float x) {
    float y; asm("tanh.approx.f32 %0, %1;" : "=f"(y) : "f"(x)); return y;
}
__device__ __forceinline__ void ffma2(unsigned long long& d,
                                      unsigned long long a, unsigned long long b) {
    asm("fma.rn.f32x2 %0, %1, %2, %0;" : "+l"(d) : "l"(a), "l"(b));
}
__device__ __forceinline__ unsigned ld_rlx(const volatile unsigned* p) {
    unsigned v;
    asm volatile("ld.relaxed.gpu.u32 %0, [%1];"
                 : "=r"(v) : "l"((const unsigned*)p) : "memory");
    return v;
}
__device__ __forceinline__ void st_rel(volatile unsigned* p, unsigned v) {
    asm volatile("st.release.gpu.u32 [%0], %1;"
                 :: "l"((unsigned*)p), "r"(v) : "memory");
}

// ---- K1a: MT[d][j] = sum_h Wih0[j,h] * Winit[h,d] --------------------------
__global__ void k1_mt(const float* __restrict__ Wih, const float* __restrict__ Winit) {
    int d = (blockIdx.x & 7) * 32 + (threadIdx.x & 31);
    int j = (blockIdx.x >> 3) * 8 + (threadIdx.x >> 5);
    const float* wr = Wih + (size_t)j * 256;
    float s = 0.f;
#pragma unroll 4
    for (int h = 0; h < 256; ++h)
        s = fmaf(wr[h], Winit[(size_t)h * 256 + d], s);
    g_MT[(size_t)d * 1024 + j] = s;
}

// ---- K1b: abias[j] = Wih0[j,:]·b_init + bih0[j] + bhh0[j] ------------------
__global__ void k1_bias(const float* __restrict__ Wih, const float* __restrict__ binit,
                        const float* __restrict__ bih, const float* __restrict__ bhh) {
    int j = blockIdx.x * 256 + threadIdx.x;
    const float* wr = Wih + (size_t)j * 256;
    float s = bih[j] + bhh[j];
#pragma unroll 4
    for (int h = 0; h < 256; ++h) s = fmaf(wr[h], binit[h], s);
    g_abias[j] = s;
}

// ---- K2: A0 = input @ MT + abias  (65536 x 1024 x 256 SGEMM) ---------------
__global__ __launch_bounds__(256) void k2_gemm(const float* __restrict__ A) {
    __shared__ float As[16][132];
    __shared__ float Bs[16][64];
    const int tid = threadIdx.x;
    const int rowBase = blockIdx.y * 128;
    const int colBase = blockIdx.x * 64;
    const int ty = tid >> 4, tx = tid & 15;

    float acc[8][4];
#pragma unroll
    for (int i = 0; i < 8; ++i)
#pragma unroll
        for (int c = 0; c < 4; ++c) acc[i][c] = 0.f;

    for (int kt = 0; kt < 256; kt += 16) {
#pragma unroll
        for (int rep = 0; rep < 2; ++rep) {
            int e = tid + rep * 256;
            int m = e >> 2, q = e & 3;
            float4 v = *(const float4*)(A + (size_t)(rowBase + m) * 256 + kt + q * 4);
            As[q * 4 + 0][m] = v.x; As[q * 4 + 1][m] = v.y;
            As[q * 4 + 2][m] = v.z; As[q * 4 + 3][m] = v.w;
        }
        {
            int kr = tid >> 4, q = tid & 15;
            *(float4*)&Bs[kr][q * 4] =
                *(const float4*)(g_MT + (size_t)(kt + kr) * 1024 + colBase + q * 4);
        }
        __syncthreads();
#pragma unroll
        for (int k = 0; k < 16; ++k) {
            float4 bv = *(float4*)&Bs[k][tx * 4];
            float4 a0 = *(float4*)&As[k][ty * 8];
            float4 a1 = *(float4*)&As[k][ty * 8 + 4];
#define FM(i, av) acc[i][0]=fmaf(av,bv.x,acc[i][0]); acc[i][1]=fmaf(av,bv.y,acc[i][1]); \
                  acc[i][2]=fmaf(av,bv.z,acc[i][2]); acc[i][3]=fmaf(av,bv.w,acc[i][3]);
            FM(0, a0.x) FM(1, a0.y) FM(2, a0.z) FM(3, a0.w)
            FM(4, a1.x) FM(5, a1.y) FM(6, a1.z) FM(7, a1.w)
#undef FM
        }
        __syncthreads();
    }
    float4 bias = *(const float4*)(g_abias + colBase + tx * 4);
#pragma unroll
    for (int i = 0; i < 8; ++i) {
        float4 r;
        r.x = acc[i][0] + bias.x; r.y = acc[i][1] + bias.y;
        r.z = acc[i][2] + bias.z; r.w = acc[i][3] + bias.w;
        *(float4*)(g_A0 + (size_t)(rowBase + ty * 8 + i) * 1024 + colBase + tx * 4) = r;
    }
}

// ---- K3: persistent recurrent kernel, 4 independent groups of 32 CTAs ------
// Group g (= bx>>5) owns batches [8g, 8g+8). CTA cc (= bx&31) owns hidden
// cols [8cc, 8cc+8) of BOTH layers. Phase p computes h0[p] and h1[p-1]
// with ONE group-local (32-wide) flag barrier per phase.
// Thread map: tid = kh*128 + rloc*4 + bp; kh = k-quarter, rloc = cl*4+gt
// (cl = local col 0..7, gt = gate 0..3), bp = batch-pair 0..3.
// SMEM floats: sw 0..24960 (3 mats x 32 rows x 260), sh0 24960 (+2080),
// sh1 27040 (+2080), sred 29120 (2304 ull = 4608 fl), sb1 33728 (32),
// sc0 33760 (64), sc1 33824 (64), sf 33888 (2). Total 33890 fl = 135560 B.
__global__ __launch_bounds__(512, 1) void k3_rec(
    const float* __restrict__ Wih, const float* __restrict__ Whh,
    const float* __restrict__ bih, const float* __restrict__ bhh,
    const float* __restrict__ h0in, const float* __restrict__ c0in,
    float* __restrict__ out)
{
    extern __shared__ float sm[];
    float* sw  = sm;
    float* sh0 = sm + 24960;
    float* sh1 = sm + 27040;
    unsigned long long* sred = (unsigned long long*)(sm + 29120);
    float* sb1 = sm + 33728;
    float* sc0 = sm + 33760;
    float* sc1 = sm + 33824;
    unsigned* sf = (unsigned*)(sm + 33888);

    const int tid = threadIdx.x;
    const int bx = blockIdx.x;
    const int grp = bx >> 5;            // group 0..3
    const int cc  = bx & 31;            // cta in group
    const int col0 = cc * 8;            // global col base
    const int b0g  = grp * 8;           // global batch base

    const int kh   = tid >> 7;          // 0..3 k-quarter
    const int q    = tid & 127;
    const int rloc = q >> 2;            // 0..31 local row
    const int bp   = q & 3;             // batch pair
    const int gt   = rloc & 3;          // gate (i,f,g,o)
    const int cl   = rloc >> 2;         // local col

    // persistent weights: m0=Whh0, m1=Wih1, m2=Whh1 (layer stride 262144)
    for (int e = tid; e < 6144; e += 512) {
        int m = e >> 11, rr = (e >> 6) & 31, kq = e & 63;
        int j = (rr & 3) * 256 + col0 + (rr >> 2);
        const float* base = (m == 0) ? (Whh + (size_t)j * 256)
                          : (m == 1) ? (Wih + 262144 + (size_t)j * 256)
                                     : (Whh + 262144 + (size_t)j * 256);
        *(float4*)&sw[(m * 32 + rr) * 260 + kq * 4] = *(const float4*)(base + kq * 4);
    }
    if (tid < 32) {
        int j = (tid & 3) * 256 + col0 + (tid >> 2);
        sb1[tid] = bih[1024 + j] + bhh[1024 + j];
    }
    if (tid < 64) {
        int bloc = tid >> 3, clE = tid & 7;
        int b = b0g + bloc, col = col0 + clE;
        sc0[tid] = c0in[b * 256 + col];
        sc1[tid] = c0in[8192 + b * 256 + col];
    }
    if (tid == 0) *sf = g_flags[bx * 32];
    __syncthreads();
    const unsigned f0 = *sf;
    const float b1v = sb1[rloc];

    const float* wp0 = sw + rloc * 260 + kh * 64;
    const float* wp1 = wp0 + 8320;      // +32*260
    const float* wp2 = wp0 + 16640;     // +64*260
    const int bA = bp * 2, bB = bp * 2 + 1;   // local batches
    const float* h0a = sh0 + bA * 260 + kh * 64;
    const float* h0b = sh0 + bB * 260 + kh * 64;
    const float* h1a = sh1 + bA * 260 + kh * 64;
    const float* h1b = sh1 + bB * 260 + kh * 64;
    const int slot = (rloc * 4 + bp) * 6;
    const int jrow = gt * 256 + col0 + cl;
    const size_t a0iA = (size_t)(b0g + bA) * 1024 + jrow;
    const size_t a0iB = a0iA + 1024;

    const int sbloc = tid >> 6, sk4 = tid & 63;       // staging map (512 f4)
    const int sbg = b0g + sbloc;

    for (int p = 0; p <= TT; ++p) {
        float a0vA = 0.f, a0vB = 0.f;
        if (kh == 0 && p < TT) {
            a0vA = __ldcs(g_A0 + (size_t)p * 32768 + a0iA);
            a0vB = __ldcs(g_A0 + (size_t)p * 32768 + a0iB);
        }
        // ---- stage group's h0[p-1], h1[p-2] slices into SMEM ----
        const float* s0 = (p == 0) ? h0in : g_h0buf[(p - 1) % 3];
        const float* s1 = (p <= 1) ? (h0in + 8192) : g_h1buf[(p - 1) % 3];
        {
            float4 v0 = __ldcg((const float4*)(s0 + sbg * 256 + sk4 * 4));
            float4 v1 = __ldcg((const float4*)(s1 + sbg * 256 + sk4 * 4));
            *(float4*)&sh0[sbloc * 260 + sk4 * 4] = v0;
            *(float4*)&sh1[sbloc * 260 + sk4 * 4] = v1;
        }
        __syncthreads();

        unsigned long long a0A = 0ull, a0B = 0ull, a1A = 0ull,
                           a1B = 0ull, a2A = 0ull, a2B = 0ull;
#pragma unroll
        for (int t = 0; t < 16; ++t) {
            ulonglong2 w0 = *(const ulonglong2*)(wp0 + t * 4);
            ulonglong2 w1 = *(const ulonglong2*)(wp1 + t * 4);
            ulonglong2 w2 = *(const ulonglong2*)(wp2 + t * 4);
            ulonglong2 hA = *(const ulonglong2*)(h0a + t * 4);
            ulonglong2 hB = *(const ulonglong2*)(h0b + t * 4);
            ulonglong2 gA = *(const ulonglong2*)(h1a + t * 4);
            ulonglong2 gB = *(const ulonglong2*)(h1b + t * 4);
            ffma2(a0A, w0.x, hA.x); ffma2(a0A, w0.y, hA.y);
            ffma2(a0B, w0.x, hB.x); ffma2(a0B, w0.y, hB.y);
            ffma2(a1A, w1.x, hA.x); ffma2(a1A, w1.y, hA.y);
            ffma2(a1B, w1.x, hB.x); ffma2(a1B, w1.y, hB.y);
            ffma2(a2A, w2.x, gA.x); ffma2(a2A, w2.y, gA.y);
            ffma2(a2B, w2.x, gB.x); ffma2(a2B, w2.y, gB.y);
        }
        if (kh != 0) {
            unsigned long long* d = sred + (size_t)(kh - 1) * 768;
            d[slot + 0] = a0A; d[slot + 1] = a1A; d[slot + 2] = a2A;
            d[slot + 3] = a0B; d[slot + 4] = a1B; d[slot + 5] = a2B;
        }
        __syncthreads();

        if (kh == 0) {
            float2 p0A = *(float2*)&a0A, p1A = *(float2*)&a1A, p2A = *(float2*)&a2A;
            float2 p0B = *(float2*)&a0B, p1B = *(float2*)&a1B, p2B = *(float2*)&a2B;
#pragma unroll
            for (int kk = 0; kk < 3; ++kk) {
                const unsigned long long* d = sred + (size_t)kk * 768;
                float2 q0 = *(float2*)&d[slot + 0]; p0A.x += q0.x; p0A.y += q0.y;
                float2 q1 = *(float2*)&d[slot + 1]; p1A.x += q1.x; p1A.y += q1.y;
                float2 q2 = *(float2*)&d[slot + 2]; p2A.x += q2.x; p2A.y += q2.y;
                float2 q3 = *(float2*)&d[slot + 3]; p0B.x += q3.x; p0B.y += q3.y;
                float2 q4 = *(float2*)&d[slot + 4]; p1B.x += q4.x; p1B.y += q4.y;
                float2 q5 = *(float2*)&d[slot + 5]; p2B.x += q5.x; p2B.y += q5.y;
            }
            float gv0A = a0vA + p0A.x + p0A.y;
            float gv0B = a0vB + p0B.x + p0B.y;
            float gv1A = p1A.x + p1A.y + p2A.x + p2A.y + b1v;
            float gv1B = p1B.x + p1B.y + p2B.x + p2B.y + b1v;
            float f0A = __shfl_down_sync(0xffffffffu, gv0A, 4);
            float g0A = __shfl_down_sync(0xffffffffu, gv0A, 8);
            float o0A = __shfl_down_sync(0xffffffffu, gv0A, 12);
            float f0B = __shfl_down_sync(0xffffffffu, gv0B, 4);
            float g0B = __shfl_down_sync(0xffffffffu, gv0B, 8);
            float o0B = __shfl_down_sync(0xffffffffu, gv0B, 12);
            float f1A = __shfl_down_sync(0xffffffffu, gv1A, 4);
            float g1A = __shfl_down_sync(0xffffffffu, gv1A, 8);
            float o1A = __shfl_down_sync(0xffffffffu, gv1A, 12);
            float f1B = __shfl_down_sync(0xffffffffu, gv1B, 4);
            float g1B = __shfl_down_sync(0xffffffffu, gv1B, 8);
            float o1B = __shfl_down_sync(0xffffffffu, gv1B, 12);
            if (gt == 0) {
                int ciA = bA * 8 + cl, ciB = bB * 8 + cl;
                int colg = col0 + cl;
                int bAg = b0g + bA, bBg = b0g + bB;
                if (p < TT) {
                    float cA = sc0[ciA];
                    float cnA = fmaf(sigf(f0A), cA, sigf(gv0A) * tanha(g0A));
                    sc0[ciA] = cnA;
                    __stcg(g_h0buf[p % 3] + bAg * 256 + colg, sigf(o0A) * tanha(cnA));
                    float cB = sc0[ciB];
                    float cnB = fmaf(sigf(f0B), cB, sigf(gv0B) * tanha(g0B));
                    sc0[ciB] = cnB;
                    __stcg(g_h0buf[p % 3] + bBg * 256 + colg, sigf(o0B) * tanha(cnB));
                }
                if (p >= 1) {
                    float cA = sc1[ciA];
                    float cnA = fmaf(sigf(f1A), cA, sigf(gv1A) * tanha(g1A));
                    float hnA = sigf(o1A) * tanha(cnA);
                    sc1[ciA] = cnA;
                    __stcg(g_h1buf[p % 3] + bAg * 256 + colg, hnA);
                    out[(size_t)(p - 1) * 16384 + bAg * 512 + colg] = hnA;
                    float cB = sc1[ciB];
                    float cnB = fmaf(sigf(f1B), cB, sigf(gv1B) * tanha(g1B));
                    float hnB = sigf(o1B) * tanha(cnB);
                    sc1[ciB] = cnB;
                    __stcg(g_h1buf[p % 3] + bBg * 256 + colg, hnB);
                    out[(size_t)(p - 1) * 16384 + bBg * 512 + colg] = hnB;
                }
                __threadfence();   // make h stores gpu-visible before release
            }
        }
        // ---- group-local flag barrier (32 CTAs) ----
        __syncthreads();
        unsigned tgt = f0 + (unsigned)(p + 1);
        if (tid == 0) st_rel(&g_flags[bx * 32], tgt);
        if (tid < 32) {
            while (ld_rlx(&g_flags[(grp * 32 + tid) * 32]) < tgt) { }
            __threadfence();   // acquire
        }
        __syncthreads();
    }
}

// ---- K4: backward half = h1[T-1] broadcast over t --------------------------
__global__ void k4_fill(float* __restrict__ out) {
    size_t i = (size_t)blockIdx.x * 256 + threadIdx.x;   // over 2048*32*64 f4
    int u4 = (int)(i & 63);
    size_t tb = i >> 6;
    int b = (int)(tb & 31);
    float4 v = *(const float4*)(out + (size_t)2047 * 16384 + b * 512 + u4 * 4);
    *(float4*)(out + tb * 512 + 256 + u4 * 4) = v;
}

extern "C" void kernel_launch(void* const* d_in, const int* in_sizes, int n_in,
                              void* d_out, int out_size) {
    const float* input = (const float*)d_in[0];
    const float* Winit = (const float*)d_in[1];
    const float* binit = (const float*)d_in[2];
    const float* Wih   = (const float*)d_in[3];
    const float* Whh   = (const float*)d_in[4];
    const float* bih   = (const float*)d_in[5];
    const float* bhh   = (const float*)d_in[6];
    const float* h0in  = (const float*)d_in[7];
    const float* c0in  = (const float*)d_in[8];
    float* out = (float*)d_out;

    cudaFuncSetAttribute(k3_rec, cudaFuncAttributeMaxDynamicSharedMemorySize, 135560);

    k1_mt<<<1024, 256>>>(Wih, Winit);
    k1_bias<<<4, 256>>>(Wih, binit, bih, bhh);
    k2_gemm<<<dim3(16, 512), 256>>>(input);
    k3_rec<<<128, 512, 135560>>>(Wih, Whh, bih, bhh, h0in, c0in, out);
    k4_fill<<<16384, 256>>>(out);
}

// round 8
// speedup vs baseline: 1.3844x; 1.1137x over previous
#include <cuda_runtime.h>
#include <math.h>

#define TT 2048

__device__ float g_MT[256 * 1024];                    // folded init matrix, [d][j]
__device__ float g_abias[1024];                       // folded layer0 bias
__device__ float g_A0[(size_t)TT * 32 * 1024];        // layer0 input gates [t][b][j]
__device__ float g_h0buf[3][32 * 256];
__device__ float g_h1buf[3][32 * 256];
__device__ unsigned g_ctr[128];                       // per-group counters (stride 32)

__device__ __forceinline__ float sigf(float x) {
    return __fdividef(1.f, 1.f + __expf(-x));
}
__device__ __forceinline__ float tanha(float x) {
    float y; asm("tanh.approx.f32 %0, %1;" : "=f"(y) : "f"(x)); return y;
}
__device__ __forceinline__ void ffma2(unsigned long long& d,
                                      unsigned long long a, unsigned long long b) {
    asm("fma.rn.f32x2 %0, %1, %2, %0;" : "+l"(d) : "l"(a), "l"(b));
}
__device__ __forceinline__ unsigned ld_rlx(const unsigned* p) {
    unsigned v;
    asm volatile("ld.relaxed.gpu.u32 %0, [%1];" : "=r"(v) : "l"(p) : "memory");
    return v;
}

// ---- K0: zero group counters (every launch, before k3) ---------------------
__global__ void k0_zero() {
    if (threadIdx.x < 128) g_ctr[threadIdx.x] = 0;
}

// ---- K1a: MT[d][j] = sum_h Wih0[j,h] * Winit[h,d] --------------------------
__global__ void k1_mt(const float* __restrict__ Wih, const float* __restrict__ Winit) {
    int d = (blockIdx.x & 7) * 32 + (threadIdx.x & 31);
    int j = (blockIdx.x >> 3) * 8 + (threadIdx.x >> 5);
    const float* wr = Wih + (size_t)j * 256;
    float s = 0.f;
#pragma unroll 4
    for (int h = 0; h < 256; ++h)
        s = fmaf(wr[h], Winit[(size_t)h * 256 + d], s);
    g_MT[(size_t)d * 1024 + j] = s;
}

// ---- K1b: abias[j] = Wih0[j,:]·b_init + bih0[j] + bhh0[j] ------------------
__global__ void k1_bias(const float* __restrict__ Wih, const float* __restrict__ binit,
                        const float* __restrict__ bih, const float* __restrict__ bhh) {
    int j = blockIdx.x * 256 + threadIdx.x;
    const float* wr = Wih + (size_t)j * 256;
    float s = bih[j] + bhh[j];
#pragma unroll 4
    for (int h = 0; h < 256; ++h) s = fmaf(wr[h], binit[h], s);
    g_abias[j] = s;
}

// ---- K2: A0 = input @ MT + abias  (65536 x 1024 x 256 SGEMM) ---------------
__global__ __launch_bounds__(256) void k2_gemm(const float* __restrict__ A) {
    __shared__ float As[16][132];
    __shared__ float Bs[16][64];
    const int tid = threadIdx.x;
    const int rowBase = blockIdx.y * 128;
    const int colBase = blockIdx.x * 64;
    const int ty = tid >> 4, tx = tid & 15;

    float acc[8][4];
#pragma unroll
    for (int i = 0; i < 8; ++i)
#pragma unroll
        for (int c = 0; c < 4; ++c) acc[i][c] = 0.f;

    for (int kt = 0; kt < 256; kt += 16) {
#pragma unroll
        for (int rep = 0; rep < 2; ++rep) {
            int e = tid + rep * 256;
            int m = e >> 2, q = e & 3;
            float4 v = *(const float4*)(A + (size_t)(rowBase + m) * 256 + kt + q * 4);
            As[q * 4 + 0][m] = v.x; As[q * 4 + 1][m] = v.y;
            As[q * 4 + 2][m] = v.z; As[q * 4 + 3][m] = v.w;
        }
        {
            int kr = tid >> 4, q = tid & 15;
            *(float4*)&Bs[kr][q * 4] =
                *(const float4*)(g_MT + (size_t)(kt + kr) * 1024 + colBase + q * 4);
        }
        __syncthreads();
#pragma unroll
        for (int k = 0; k < 16; ++k) {
            float4 bv = *(float4*)&Bs[k][tx * 4];
            float4 a0 = *(float4*)&As[k][ty * 8];
            float4 a1 = *(float4*)&As[k][ty * 8 + 4];
#define FM(i, av) acc[i][0]=fmaf(av,bv.x,acc[i][0]); acc[i][1]=fmaf(av,bv.y,acc[i][1]); \
                  acc[i][2]=fmaf(av,bv.z,acc[i][2]); acc[i][3]=fmaf(av,bv.w,acc[i][3]);
            FM(0, a0.x) FM(1, a0.y) FM(2, a0.z) FM(3, a0.w)
            FM(4, a1.x) FM(5, a1.y) FM(6, a1.z) FM(7, a1.w)
#undef FM
        }
        __syncthreads();
    }
    float4 bias = *(const float4*)(g_abias + colBase + tx * 4);
#pragma unroll
    for (int i = 0; i < 8; ++i) {
        float4 r;
        r.x = acc[i][0] + bias.x; r.y = acc[i][1] + bias.y;
        r.z = acc[i][2] + bias.z; r.w = acc[i][3] + bias.w;
        *(float4*)(g_A0 + (size_t)(rowBase + ty * 8 + i) * 1024 + colBase + tx * 4) = r;
    }
}

// ---- K3: persistent recurrent kernel, 4 independent groups of 32 CTAs ------
// Group g (= bx>>5) owns batches [8g, 8g+8). CTA cc (= bx&31) owns hidden
// cols [8cc, 8cc+8) of BOTH layers. Phase p computes h0[p] and h1[p-1].
// Sync: parallel 128-thread tail -> RED counter -> single-line poll.
// SMEM floats: sw 0 (24960), sh0 24960 (2080), sh1 27040 (2080),
// sred 29120 (4608), sb1 33728 (32), sc0 33760 (64), sc1 33824 (64),
// sgate 33888 (524). Total 34412 fl = 137648 B.
__global__ __launch_bounds__(512, 1) void k3_rec(
    const float* __restrict__ Wih, const float* __restrict__ Whh,
    const float* __restrict__ bih, const float* __restrict__ bhh,
    const float* __restrict__ h0in, const float* __restrict__ c0in,
    float* __restrict__ out)
{
    extern __shared__ float sm[];
    float* sw  = sm;
    float* sh0 = sm + 24960;
    float* sh1 = sm + 27040;
    unsigned long long* sred = (unsigned long long*)(sm + 29120);
    float* sb1 = sm + 33728;
    float* sc0 = sm + 33760;
    float* sc1 = sm + 33824;
    float* sgate = sm + 33888;          // 4 arrays at +0,+132,+264,+396

    const int tid = threadIdx.x;
    const int bx = blockIdx.x;
    const int grp = bx >> 5;            // group 0..3
    const int cc  = bx & 31;            // cta in group
    const int col0 = cc * 8;            // global col base
    const int b0g  = grp * 8;           // global batch base

    const int kh   = tid >> 7;          // 0..3 k-quarter
    const int q    = tid & 127;
    const int rloc = q >> 2;            // 0..31 local row (cl*4+gt)
    const int bp   = q & 3;             // batch pair

    // persistent weights: m0=Whh0, m1=Wih1, m2=Whh1 (layer stride 262144)
    for (int e = tid; e < 6144; e += 512) {
        int m = e >> 11, rr = (e >> 6) & 31, kq = e & 63;
        int j = (rr & 3) * 256 + col0 + (rr >> 2);
        const float* base = (m == 0) ? (Whh + (size_t)j * 256)
                          : (m == 1) ? (Wih + 262144 + (size_t)j * 256)
                                     : (Whh + 262144 + (size_t)j * 256);
        *(float4*)&sw[(m * 32 + rr) * 260 + kq * 4] = *(const float4*)(base + kq * 4);
    }
    if (tid < 32) {
        int j = (tid & 3) * 256 + col0 + (tid >> 2);
        sb1[tid] = bih[1024 + j] + bhh[1024 + j];
    }
    if (tid < 64) {
        int bloc = tid >> 3, clE = tid & 7;
        int b = b0g + bloc, col = col0 + clE;
        sc0[tid] = c0in[b * 256 + col];
        sc1[tid] = c0in[8192 + b * 256 + col];
    }
    __syncthreads();
    const float b1v = sb1[rloc];

    const float* wp0 = sw + rloc * 260 + kh * 64;
    const float* wp1 = wp0 + 8320;      // +32*260
    const float* wp2 = wp0 + 16640;     // +64*260
    const int bA = bp * 2, bB = bp * 2 + 1;   // local batches
    const float* h0a = sh0 + bA * 260 + kh * 64;
    const float* h0b = sh0 + bB * 260 + kh * 64;
    const float* h1a = sh1 + bA * 260 + kh * 64;
    const float* h1b = sh1 + bB * 260 + kh * 64;
    const int slot = (rloc * 4 + bp) * 6;
    const int jrow = (rloc & 3) * 256 + col0 + (rloc >> 2);
    const size_t a0iA = (size_t)(b0g + bA) * 1024 + jrow;
    const size_t a0iB = a0iA + 1024;

    const int sbloc = tid >> 6, sk4 = tid & 63;       // staging map (512 f4)
    const int sbg = b0g + sbloc;

    // tail map: one cell per kh==0 thread
    const int tlayer = q >> 6;          // 0 or 1
    const int tcell = q & 63;
    const int tcl = tcell >> 3, tb = tcell & 7;
    const int tbp = tb >> 1;
    const int tgbase = ((tb & 1) ? 132 : 0) + (tlayer ? 264 : 0);
    const int tci = tb * 8 + tcl;
    const int tcolg = col0 + tcl;
    const int tbg = b0g + tb;

    unsigned* ctr = &g_ctr[grp * 32];

    for (int p = 0; p <= TT; ++p) {
        float a0vA = 0.f, a0vB = 0.f;
        if (kh == 0 && p < TT) {
            a0vA = __ldcs(g_A0 + (size_t)p * 32768 + a0iA);
            a0vB = __ldcs(g_A0 + (size_t)p * 32768 + a0iB);
        }
        // ---- stage group's h0[p-1], h1[p-2] slices into SMEM ----
        const float* s0 = (p == 0) ? h0in : g_h0buf[(p - 1) % 3];
        const float* s1 = (p <= 1) ? (h0in + 8192) : g_h1buf[(p - 1) % 3];
        {
            float4 v0 = __ldcg((const float4*)(s0 + sbg * 256 + sk4 * 4));
            float4 v1 = __ldcg((const float4*)(s1 + sbg * 256 + sk4 * 4));
            *(float4*)&sh0[sbloc * 260 + sk4 * 4] = v0;
            *(float4*)&sh1[sbloc * 260 + sk4 * 4] = v1;
        }
        __syncthreads();

        unsigned long long a0A = 0ull, a0B = 0ull, a1A = 0ull,
                           a1B = 0ull, a2A = 0ull, a2B = 0ull;
#pragma unroll
        for (int t = 0; t < 16; ++t) {
            ulonglong2 w0 = *(const ulonglong2*)(wp0 + t * 4);
            ulonglong2 w1 = *(const ulonglong2*)(wp1 + t * 4);
            ulonglong2 w2 = *(const ulonglong2*)(wp2 + t * 4);
            ulonglong2 hA = *(const ulonglong2*)(h0a + t * 4);
            ulonglong2 hB = *(const ulonglong2*)(h0b + t * 4);
            ulonglong2 gA = *(const ulonglong2*)(h1a + t * 4);
            ulonglong2 gB = *(const ulonglong2*)(h1b + t * 4);
            ffma2(a0A, w0.x, hA.x); ffma2(a0A, w0.y, hA.y);
            ffma2(a0B, w0.x, hB.x); ffma2(a0B, w0.y, hB.y);
            ffma2(a1A, w1.x, hA.x); ffma2(a1A, w1.y, hA.y);
            ffma2(a1B, w1.x, hB.x); ffma2(a1B, w1.y, hB.y);
            ffma2(a2A, w2.x, gA.x); ffma2(a2A, w2.y, gA.y);
            ffma2(a2B, w2.x, gB.x); ffma2(a2B, w2.y, gB.y);
        }
        if (kh != 0) {
            unsigned long long* d = sred + (size_t)(kh - 1) * 768;
            d[slot + 0] = a0A; d[slot + 1] = a1A; d[slot + 2] = a2A;
            d[slot + 3] = a0B; d[slot + 4] = a1B; d[slot + 5] = a2B;
        }
        __syncthreads();

        if (kh == 0) {
            float2 p0A = *(float2*)&a0A, p1A = *(float2*)&a1A, p2A = *(float2*)&a2A;
            float2 p0B = *(float2*)&a0B, p1B = *(float2*)&a1B, p2B = *(float2*)&a2B;
#pragma unroll
            for (int kk = 0; kk < 3; ++kk) {
                const unsigned long long* d = sred + (size_t)kk * 768;
                float2 q0 = *(float2*)&d[slot + 0]; p0A.x += q0.x; p0A.y += q0.y;
                float2 q1 = *(float2*)&d[slot + 1]; p1A.x += q1.x; p1A.y += q1.y;
                float2 q2 = *(float2*)&d[slot + 2]; p2A.x += q2.x; p2A.y += q2.y;
                float2 q3 = *(float2*)&d[slot + 3]; p0B.x += q3.x; p0B.y += q3.y;
                float2 q4 = *(float2*)&d[slot + 4]; p1B.x += q4.x; p1B.y += q4.y;
                float2 q5 = *(float2*)&d[slot + 5]; p2B.x += q5.x; p2B.y += q5.y;
            }
            int gidx = rloc * 4 + bp;
            sgate[gidx + 0]   = a0vA + p0A.x + p0A.y;
            sgate[gidx + 132] = a0vB + p0B.x + p0B.y;
            sgate[gidx + 264] = p1A.x + p1A.y + p2A.x + p2A.y + b1v;
            sgate[gidx + 396] = p1B.x + p1B.y + p2B.x + p2B.y + b1v;
            asm volatile("bar.sync 1, 128;" ::: "memory");

            // ---- parallel tail: one cell per thread ----
            float gi = sgate[tgbase + (tcl * 4 + 0) * 4 + tbp];
            float gf = sgate[tgbase + (tcl * 4 + 1) * 4 + tbp];
            float gg = sgate[tgbase + (tcl * 4 + 2) * 4 + tbp];
            float go = sgate[tgbase + (tcl * 4 + 3) * 4 + tbp];
            if (tlayer == 0) {
                if (p < TT) {
                    float c = sc0[tci];
                    float cn = fmaf(sigf(gf), c, sigf(gi) * tanha(gg));
                    sc0[tci] = cn;
                    __stcg(g_h0buf[p % 3] + tbg * 256 + tcolg, sigf(go) * tanha(cn));
                    __threadfence();
                }
            } else {
                if (p >= 1) {
                    float c = sc1[tci];
                    float cn = fmaf(sigf(gf), c, sigf(gi) * tanha(gg));
                    float hn = sigf(go) * tanha(cn);
                    sc1[tci] = cn;
                    __stcg(g_h1buf[p % 3] + tbg * 256 + tcolg, hn);
                    __threadfence();
                    out[(size_t)(p - 1) * 16384 + tbg * 512 + tcolg] = hn;
                }
            }
            asm volatile("bar.sync 1, 128;" ::: "memory");
        }
        // ---- counter barrier (32 CTAs per group, single L2 line) ----
        if (tid == 0) {
            atomicAdd(ctr, 1u);               // RED (result unused)
            unsigned tgt = 32u * (unsigned)(p + 1);
            while (ld_rlx(ctr) < tgt) { }
            __threadfence();                  // acquire
        }
        __syncthreads();
    }
}

// ---- K4: backward half = h1[T-1] broadcast over t --------------------------
__global__ void k4_fill(float* __restrict__ out) {
    size_t i = (size_t)blockIdx.x * 256 + threadIdx.x;   // over 2048*32*64 f4
    int u4 = (int)(i & 63);
    size_t tb = i >> 6;
    int b = (int)(tb & 31);
    float4 v = *(const float4*)(out + (size_t)2047 * 16384 + b * 512 + u4 * 4);
    *(float4*)(out + tb * 512 + 256 + u4 * 4) = v;
}

extern "C" void kernel_launch(void* const* d_in, const int* in_sizes, int n_in,
                              void* d_out, int out_size) {
    const float* input = (const float*)d_in[0];
    const float* Winit = (const float*)d_in[1];
    const float* binit = (const float*)d_in[2];
    const float* Wih   = (const float*)d_in[3];
    const float* Whh   = (const float*)d_in[4];
    const float* bih   = (const float*)d_in[5];
    const float* bhh   = (const float*)d_in[6];
    const float* h0in  = (const float*)d_in[7];
    const float* c0in  = (const float*)d_in[8];
    float* out = (float*)d_out;

    cudaFuncSetAttribute(k3_rec, cudaFuncAttributeMaxDynamicSharedMemorySize, 137648);

    k0_zero<<<1, 128>>>();
    k1_mt<<<1024, 256>>>(Wih, Winit);
    k1_bias<<<4, 256>>>(Wih, binit, bih, bhh);
    k2_gemm<<<dim3(16, 512), 256>>>(input);
    k3_rec<<<128, 512, 137648>>>(Wih, Whh, bih, bhh, h0in, c0in, out);
    k4_fill<<<16384, 256>>>(out);
}

// round 9
// speedup vs baseline: 1.5501x; 1.1197x over previous
#include <cuda_runtime.h>
#include <math.h>

#define TT 2048

__device__ float g_MT[256 * 1024];                    // folded init matrix, [d][j]
__device__ float g_abias[1024];                       // folded layer0 bias
__device__ float g_A0[(size_t)TT * 32 * 1024];        // layer0 input gates [t][b][j]
// per-producer h slices: [slot 3][grp 4][cc 32][layer 2][b 8][c 8]
__device__ float g_hbuf[3 * 4 * 32 * 128];
__device__ unsigned g_tags[4096];                     // (grp*32+cc)*32, 128B padded

__device__ __forceinline__ float sigf(float x) {
    return __fdividef(1.f, 1.f + __expf(-x));
}
__device__ __forceinline__ float tanha(float x) {
    float y; asm("tanh.approx.f32 %0, %1;" : "=f"(y) : "f"(x)); return y;
}
__device__ __forceinline__ void ffma2(unsigned long long& d,
                                      unsigned long long a, unsigned long long b) {
    asm("fma.rn.f32x2 %0, %1, %2, %0;" : "+l"(d) : "l"(a), "l"(b));
}
__device__ __forceinline__ unsigned ld_acq(const unsigned* p) {
    unsigned v;
    asm volatile("ld.acquire.gpu.u32 %0, [%1];" : "=r"(v) : "l"(p) : "memory");
    return v;
}
__device__ __forceinline__ void st_rlx(unsigned* p, unsigned v) {
    asm volatile("st.relaxed.gpu.u32 [%0], %1;" :: "l"(p), "r"(v) : "memory");
}

// ---- K0: zero tags (every launch, before k3) -------------------------------
__global__ void k0_zero() {
    g_tags[blockIdx.x * 256 + threadIdx.x] = 0;
}

// ---- K1a: MT[d][j] = sum_h Wih0[j,h] * Winit[h,d] --------------------------
__global__ void k1_mt(const float* __restrict__ Wih, const float* __restrict__ Winit) {
    int d = (blockIdx.x & 7) * 32 + (threadIdx.x & 31);
    int j = (blockIdx.x >> 3) * 8 + (threadIdx.x >> 5);
    const float* wr = Wih + (size_t)j * 256;
    float s = 0.f;
#pragma unroll 4
    for (int h = 0; h < 256; ++h)
        s = fmaf(wr[h], Winit[(size_t)h * 256 + d], s);
    g_MT[(size_t)d * 1024 + j] = s;
}

// ---- K1b: abias[j] = Wih0[j,:]·b_init + bih0[j] + bhh0[j] ------------------
__global__ void k1_bias(const float* __restrict__ Wih, const float* __restrict__ binit,
                        const float* __restrict__ bih, const float* __restrict__ bhh) {
    int j = blockIdx.x * 256 + threadIdx.x;
    const float* wr = Wih + (size_t)j * 256;
    float s = bih[j] + bhh[j];
#pragma unroll 4
    for (int h = 0; h < 256; ++h) s = fmaf(wr[h], binit[h], s);
    g_abias[j] = s;
}

// ---- K2: A0 = input @ MT + abias  (65536 x 1024 x 256 SGEMM) ---------------
__global__ __launch_bounds__(256) void k2_gemm(const float* __restrict__ A) {
    __shared__ float As[16][132];
    __shared__ float Bs[16][64];
    const int tid = threadIdx.x;
    const int rowBase = blockIdx.y * 128;
    const int colBase = blockIdx.x * 64;
    const int ty = tid >> 4, tx = tid & 15;

    float acc[8][4];
#pragma unroll
    for (int i = 0; i < 8; ++i)
#pragma unroll
        for (int c = 0; c < 4; ++c) acc[i][c] = 0.f;

    for (int kt = 0; kt < 256; kt += 16) {
#pragma unroll
        for (int rep = 0; rep < 2; ++rep) {
            int e = tid + rep * 256;
            int m = e >> 2, q = e & 3;
            float4 v = *(const float4*)(A + (size_t)(rowBase + m) * 256 + kt + q * 4);
            As[q * 4 + 0][m] = v.x; As[q * 4 + 1][m] = v.y;
            As[q * 4 + 2][m] = v.z; As[q * 4 + 3][m] = v.w;
        }
        {
            int kr = tid >> 4, q = tid & 15;
            *(float4*)&Bs[kr][q * 4] =
                *(const float4*)(g_MT + (size_t)(kt + kr) * 1024 + colBase + q * 4);
        }
        __syncthreads();
#pragma unroll
        for (int k = 0; k < 16; ++k) {
            float4 bv = *(float4*)&Bs[k][tx * 4];
            float4 a0 = *(float4*)&As[k][ty * 8];
            float4 a1 = *(float4*)&As[k][ty * 8 + 4];
#define FM(i, av) acc[i][0]=fmaf(av,bv.x,acc[i][0]); acc[i][1]=fmaf(av,bv.y,acc[i][1]); \
                  acc[i][2]=fmaf(av,bv.z,acc[i][2]); acc[i][3]=fmaf(av,bv.w,acc[i][3]);
            FM(0, a0.x) FM(1, a0.y) FM(2, a0.z) FM(3, a0.w)
            FM(4, a1.x) FM(5, a1.y) FM(6, a1.z) FM(7, a1.w)
#undef FM
        }
        __syncthreads();
    }
    float4 bias = *(const float4*)(g_abias + colBase + tx * 4);
#pragma unroll
    for (int i = 0; i < 8; ++i) {
        float4 r;
        r.x = acc[i][0] + bias.x; r.y = acc[i][1] + bias.y;
        r.z = acc[i][2] + bias.z; r.w = acc[i][3] + bias.w;
        *(float4*)(g_A0 + (size_t)(rowBase + ty * 8 + i) * 1024 + colBase + tx * 4) = r;
    }
}

// ---- K3: persistent recurrent kernel, per-producer dataflow tags -----------
// 4 groups x 32 CTAs. Group g owns batches [8g,8g+8); CTA cc owns cols
// [8cc,8cc+8) of BOTH layers. Phase p computes h0[p] and h1[p-1].
// No group barrier: producers publish 128-float slices + tag; consumers
// poll per-producer tags with acquire loads. 3-slot rotation is safe
// because staging phase p requires ALL tags >= p (self-bounded skew).
// SMEM floats: sw 0 (24960), sh0 24960 (2080), sh1 27040 (2080),
// sred 29120 (4608), sb1 33728 (32), sc0 33760 (64), sc1 33824 (64),
// sgate 33888 (524). Total 34412 fl = 137648 B.
__global__ __launch_bounds__(512, 1) void k3_rec(
    const float* __restrict__ Wih, const float* __restrict__ Whh,
    const float* __restrict__ bih, const float* __restrict__ bhh,
    const float* __restrict__ h0in, const float* __restrict__ c0in,
    float* __restrict__ out)
{
    extern __shared__ float sm[];
    float* sw  = sm;
    float* sh0 = sm + 24960;
    float* sh1 = sm + 27040;
    unsigned long long* sred = (unsigned long long*)(sm + 29120);
    float* sb1 = sm + 33728;
    float* sc0 = sm + 33760;
    float* sc1 = sm + 33824;
    float* sgate = sm + 33888;          // 4 arrays at +0,+132,+264,+396

    const int tid = threadIdx.x;
    const int bx = blockIdx.x;
    const int grp = bx >> 5;            // group 0..3
    const int cc  = bx & 31;            // cta in group
    const int col0 = cc * 8;            // global col base
    const int b0g  = grp * 8;           // global batch base

    const int kh   = tid >> 7;          // 0..3 k-quarter
    const int q    = tid & 127;
    const int rloc = q >> 2;            // 0..31 local row (cl*4+gt)
    const int bp   = q & 3;             // batch pair

    // persistent weights: m0=Whh0, m1=Wih1, m2=Whh1 (layer stride 262144)
    for (int e = tid; e < 6144; e += 512) {
        int m = e >> 11, rr = (e >> 6) & 31, kq = e & 63;
        int j = (rr & 3) * 256 + col0 + (rr >> 2);
        const float* base = (m == 0) ? (Whh + (size_t)j * 256)
                          : (m == 1) ? (Wih + 262144 + (size_t)j * 256)
                                     : (Whh + 262144 + (size_t)j * 256);
        *(float4*)&sw[(m * 32 + rr) * 260 + kq * 4] = *(const float4*)(base + kq * 4);
    }
    if (tid < 32) {
        int j = (tid & 3) * 256 + col0 + (tid >> 2);
        sb1[tid] = bih[1024 + j] + bhh[1024 + j];
    }
    if (tid < 64) {
        int bloc = tid >> 3, clE = tid & 7;
        int b = b0g + bloc, col = col0 + clE;
        sc0[tid] = c0in[b * 256 + col];
        sc1[tid] = c0in[8192 + b * 256 + col];
    }
    __syncthreads();
    const float b1v = sb1[rloc];

    const float* wp0 = sw + rloc * 260 + kh * 64;
    const float* wp1 = wp0 + 8320;      // +32*260
    const float* wp2 = wp0 + 16640;     // +64*260
    const int bA = bp * 2, bB = bp * 2 + 1;   // local batches
    const float* h0a = sh0 + bA * 260 + kh * 64;
    const float* h0b = sh0 + bB * 260 + kh * 64;
    const float* h1a = sh1 + bA * 260 + kh * 64;
    const float* h1b = sh1 + bB * 260 + kh * 64;
    const int slot = (rloc * 4 + bp) * 6;
    const int jrow = (rloc & 3) * 256 + col0 + (rloc >> 2);
    const size_t a0iA = (size_t)(b0g + bA) * 1024 + jrow;
    const size_t a0iB = a0iA + 1024;

    // staging map: 16 threads per producer (layer x 8 local batches)
    const int pc  = tid >> 4;           // producer cta 0..31
    const int sub = tid & 15;
    const int lay = sub >> 3;           // 0 = h0, 1 = h1
    const int sb  = sub & 7;            // local batch
    float* sdst = (lay ? sh1 : sh0) + sb * 260 + pc * 8;
    const unsigned* tagp = g_tags + (grp * 32 + pc) * 32;
    const float* initsrc = h0in + lay * 8192 + (size_t)(b0g + sb) * 256 + pc * 8;
    const float* slicebase = g_hbuf + grp * 4096 + pc * 128 + lay * 64 + sb * 8;

    // tail map: one cell per kh==0 thread
    const int tlayer = q >> 6;          // 0 or 1
    const int tcell = q & 63;
    const int tcl = tcell >> 3, tb = tcell & 7;
    const int tbp = tb >> 1;
    const int tgbase = ((tb & 1) ? 132 : 0) + (tlayer ? 264 : 0);
    const int tci = tb * 8 + tcl;
    const int tcolg = col0 + tcl;
    const int tbg = b0g + tb;
    float* myslice = g_hbuf + grp * 4096 + cc * 128 + tlayer * 64 + tb * 8 + tcl;
    unsigned* mytag = g_tags + (grp * 32 + cc) * 32;

    for (int p = 0; p <= TT; ++p) {
        float a0vA = 0.f, a0vB = 0.f;
        if (kh == 0 && p < TT) {
            a0vA = __ldcs(g_A0 + (size_t)p * 32768 + a0iA);
            a0vB = __ldcs(g_A0 + (size_t)p * 32768 + a0iB);
        }
        // ---- dataflow staging: poll producer tag, fetch 32B slice ----
        const bool fromInit = lay ? (p <= 1) : (p == 0);
        if (fromInit) {
            float4 v0 = *(const float4*)(initsrc);
            float4 v1 = *(const float4*)(initsrc + 4);
            *(float4*)(sdst) = v0;
            *(float4*)(sdst + 4) = v1;
        } else {
            while (ld_acq(tagp) < (unsigned)p) { }
            const float* sp = slicebase + ((p + 2) % 3) * 16384;
            float4 v0 = __ldcg((const float4*)sp);
            float4 v1 = __ldcg((const float4*)(sp + 4));
            *(float4*)(sdst) = v0;
            *(float4*)(sdst + 4) = v1;
        }
        __syncthreads();

        unsigned long long a0A = 0ull, a0B = 0ull, a1A = 0ull,
                           a1B = 0ull, a2A = 0ull, a2B = 0ull;
#pragma unroll
        for (int t = 0; t < 16; ++t) {
            ulonglong2 w0 = *(const ulonglong2*)(wp0 + t * 4);
            ulonglong2 w1 = *(const ulonglong2*)(wp1 + t * 4);
            ulonglong2 w2 = *(const ulonglong2*)(wp2 + t * 4);
            ulonglong2 hA = *(const ulonglong2*)(h0a + t * 4);
            ulonglong2 hB = *(const ulonglong2*)(h0b + t * 4);
            ulonglong2 gA = *(const ulonglong2*)(h1a + t * 4);
            ulonglong2 gB = *(const ulonglong2*)(h1b + t * 4);
            ffma2(a0A, w0.x, hA.x); ffma2(a0A, w0.y, hA.y);
            ffma2(a0B, w0.x, hB.x); ffma2(a0B, w0.y, hB.y);
            ffma2(a1A, w1.x, hA.x); ffma2(a1A, w1.y, hA.y);
            ffma2(a1B, w1.x, hB.x); ffma2(a1B, w1.y, hB.y);
            ffma2(a2A, w2.x, gA.x); ffma2(a2A, w2.y, gA.y);
            ffma2(a2B, w2.x, gB.x); ffma2(a2B, w2.y, gB.y);
        }
        if (kh != 0) {
            unsigned long long* d = sred + (size_t)(kh - 1) * 768;
            d[slot + 0] = a0A; d[slot + 1] = a1A; d[slot + 2] = a2A;
            d[slot + 3] = a0B; d[slot + 4] = a1B; d[slot + 5] = a2B;
        }
        __syncthreads();
        // kh!=0 warps fall through to next-phase staging here (overlaps tail)

        if (kh == 0) {
            float2 p0A = *(float2*)&a0A, p1A = *(float2*)&a1A, p2A = *(float2*)&a2A;
            float2 p0B = *(float2*)&a0B, p1B = *(float2*)&a1B, p2B = *(float2*)&a2B;
#pragma unroll
            for (int kk = 0; kk < 3; ++kk) {
                const unsigned long long* d = sred + (size_t)kk * 768;
                float2 q0 = *(float2*)&d[slot + 0]; p0A.x += q0.x; p0A.y += q0.y;
                float2 q1 = *(float2*)&d[slot + 1]; p1A.x += q1.x; p1A.y += q1.y;
                float2 q2 = *(float2*)&d[slot + 2]; p2A.x += q2.x; p2A.y += q2.y;
                float2 q3 = *(float2*)&d[slot + 3]; p0B.x += q3.x; p0B.y += q3.y;
                float2 q4 = *(float2*)&d[slot + 4]; p1B.x += q4.x; p1B.y += q4.y;
                float2 q5 = *(float2*)&d[slot + 5]; p2B.x += q5.x; p2B.y += q5.y;
            }
            int gidx = rloc * 4 + bp;
            sgate[gidx + 0]   = a0vA + p0A.x + p0A.y;
            sgate[gidx + 132] = a0vB + p0B.x + p0B.y;
            sgate[gidx + 264] = p1A.x + p1A.y + p2A.x + p2A.y + b1v;
            sgate[gidx + 396] = p1B.x + p1B.y + p2B.x + p2B.y + b1v;
            asm volatile("bar.sync 1, 128;" ::: "memory");

            // ---- parallel tail: one cell per thread ----
            float gi = sgate[tgbase + (tcl * 4 + 0) * 4 + tbp];
            float gf = sgate[tgbase + (tcl * 4 + 1) * 4 + tbp];
            float gg = sgate[tgbase + (tcl * 4 + 2) * 4 + tbp];
            float go = sgate[tgbase + (tcl * 4 + 3) * 4 + tbp];
            if (tlayer == 0) {
                if (p < TT) {
                    float c = sc0[tci];
                    float cn = fmaf(sigf(gf), c, sigf(gi) * tanha(gg));
                    sc0[tci] = cn;
                    __stcg(myslice + (p % 3) * 16384, sigf(go) * tanha(cn));
                }
            } else {
                if (p >= 1) {
                    float c = sc1[tci];
                    float cn = fmaf(sigf(gf), c, sigf(gi) * tanha(gg));
                    float hn = sigf(go) * tanha(cn);
                    sc1[tci] = cn;
                    __stcg(myslice + (p % 3) * 16384, hn);
                    out[(size_t)(p - 1) * 16384 + tbg * 512 + tcolg] = hn;
                }
            }
            asm volatile("bar.sync 1, 128;" ::: "memory");
            if (tid == 0) {
                __threadfence();                         // drain h-slice stores
                st_rlx(mytag, (unsigned)(p + 1));        // publish phase p
            }
        }
        // no group barrier: next staging self-synchronizes via tags
    }
}

// ---- K4: backward half = h1[T-1] broadcast over t --------------------------
__global__ void k4_fill(float* __restrict__ out) {
    size_t i = (size_t)blockIdx.x * 256 + threadIdx.x;   // over 2048*32*64 f4
    int u4 = (int)(i & 63);
    size_t tb = i >> 6;
    int b = (int)(tb & 31);
    float4 v = *(const float4*)(out + (size_t)2047 * 16384 + b * 512 + u4 * 4);
    *(float4*)(out + tb * 512 + 256 + u4 * 4) = v;
}

extern "C" void kernel_launch(void* const* d_in, const int* in_sizes, int n_in,
                              void* d_out, int out_size) {
    const float* input = (const float*)d_in[0];
    const float* Winit = (const float*)d_in[1];
    const float* binit = (const float*)d_in[2];
    const float* Wih   = (const float*)d_in[3];
    const float* Whh   = (const float*)d_in[4];
    const float* bih   = (const float*)d_in[5];
    const float* bhh   = (const float*)d_in[6];
    const float* h0in  = (const float*)d_in[7];
    const float* c0in  = (const float*)d_in[8];
    float* out = (float*)d_out;

    cudaFuncSetAttribute(k3_rec, cudaFuncAttributeMaxDynamicSharedMemorySize, 137648);

    k0_zero<<<16, 256>>>();
    k1_mt<<<1024, 256>>>(Wih, Winit);
    k1_bias<<<4, 256>>>(Wih, binit, bih, bhh);
    k2_gemm<<<dim3(16, 512), 256>>>(input);
    k3_rec<<<128, 512, 137648>>>(Wih, Whh, bih, bhh, h0in, c0in, out);
    k4_fill<<<16384, 256>>>(out);
}